// round 16
// baseline (speedup 1.0000x reference)
#include <cuda_runtime.h>
#include <cstdint>

// ============================================================================
// NAS LSTM controller, 32 sequential steps, single persistent kernel.
// 64 worker CTAs x 512 threads (148 launched; extras exit). Weights in SMEM.
// Cross-CTA comm: epoch-tagged u64 words (tag<<32 | float), relaxed gpu-scope.
// All consume sweeps fuse the cross-CTA reduction into warp shuffles (no
// bank-conflicted smem sums). Cell2's matvec is hidden inside the round-2
// wait (it depends only on h1, not on the node sample).
// Exact JAX threefry2x32 sampling replicated per CTA (deterministic).
// ============================================================================

#define GRID   64
#define GRIDL  148
#define NT     512
#define D      512
#define LP1    33
#define NSTEP  32
#define OPSN   16

typedef unsigned long long u64t;

// ------------------------------ global state -------------------------------
__device__ u64t gPubA[GRID * 512];   // [src][dim] attn partials
__device__ u64t gPubH1[GRID * 8];    // [src][j]   h1 slices
__device__ u64t gPubI[GRID * 8];     // init h0 slices
__device__ u64t gPubL[LP1 * GRID];   // [anchor][src] node-logit partials
__device__ u64t gPubO[GRID * 24];    // [src][0..7]=h2, [8..23]=op partials
__device__ unsigned gEpochBase;

// ------------------------------ shared layout ------------------------------
struct __align__(16) SM {
    float Whh[32 * 512];       // 64 KB  own 32 gate rows of w_hh
    float Wih[32 * 512];       // 64 KB  own 32 gate rows of w_ih
    float A1[8 * 512];         // own rows of w_attn_1
    float A2T[8 * 512];        // [j][k]: w2[k][own dim j]
    float hprev[512];
    float h1full[512];
    float embG[17 * 32];       // x-gates (incl bias) per embedding
    float anchG[LP1 * 32];     // x-gates per anchor
    float anchW1[LP1 * 8];     // own slice of anchors_w1
    float OPFT[OPSN * 8];      // op_fc[:, own 8 dims]
    float gnode[NSTEP * LP1];
    float gop[NSTEP * OPSN];
    float vals[40];
    float attnP16[16];         // per-warp hw2 partials
    float idxfc8[8];
    float bias[32];
    float gbuf[32];
    float cslice[8];
    float h2own[8];
    float oplog[16];
    unsigned keys2[NSTEP * 2];
    int nodeIdx, opIdx, sel;
    float nodeLp, nodeEnt, opLp, opEnt, lpSum, entSum;
    unsigned base;
};

// --------------------------- tagged publish/poll ---------------------------
__device__ __forceinline__ void pub64(u64t* p, float v, unsigned tag) {
    u64t w = ((u64t)tag << 32) | (u64t)__float_as_uint(v);
    asm volatile("st.relaxed.gpu.global.u64 [%0], %1;" :: "l"(p), "l"(w) : "memory");
}
__device__ __forceinline__ u64t ldrx(const u64t* p) {
    u64t w;
    asm volatile("ld.relaxed.gpu.global.u64 %0, [%1];" : "=l"(w) : "l"(p) : "memory");
    return w;
}
__device__ __forceinline__ float lo32(u64t w) { return __uint_as_float((unsigned)w); }

// ------------------------------ threefry2x32 -------------------------------
__device__ __forceinline__ void tf2x32(unsigned k0, unsigned k1,
                                       unsigned x0, unsigned x1,
                                       unsigned& o0, unsigned& o1) {
    unsigned ks2 = k0 ^ k1 ^ 0x1BD11BDAu;
    x0 += k0; x1 += k1;
#define TFR(r) { x0 += x1; x1 = (x1 << (r)) | (x1 >> (32 - (r))); x1 ^= x0; }
    TFR(13) TFR(15) TFR(26) TFR(6)   x0 += k1;  x1 += ks2 + 1u;
    TFR(17) TFR(29) TFR(16) TFR(24)  x0 += ks2; x1 += k0 + 2u;
    TFR(13) TFR(15) TFR(26) TFR(6)   x0 += k0;  x1 += k1 + 3u;
    TFR(17) TFR(29) TFR(16) TFR(24)  x0 += k1;  x1 += ks2 + 4u;
    TFR(13) TFR(15) TFR(26) TFR(6)   x0 += ks2; x1 += k0 + 5u;
#undef TFR
    o0 = x0; o1 = x1;
}

__device__ __forceinline__ float gumbelf(unsigned bits) {
    float f = __uint_as_float((bits >> 9) | 0x3f800000u) - 1.0f;
    const float tiny = 1.17549435e-38f;
    float u = fmaxf(tiny, f * (1.0f - tiny) + tiny);
    return -logf(-logf(u));
}

__device__ __forceinline__ float sigf(float x) {
    return __fdividef(1.0f, 1.0f + __expf(-x));
}
__device__ __forceinline__ float tanhfast(float x) {
    return 1.0f - __fdividef(2.0f, __expf(2.0f * x) + 1.0f);
}

// LSTM cell (combined): gates = Whh*hin + xc; tail publishes h slice early.
__device__ __forceinline__ void cell_hh(SM* s, const float* hin, const float* xc,
                                        int tid, float* houtOwn,
                                        u64t* pubBase, unsigned tag) {
    int row = tid >> 4, lane = tid & 15;
    const float4* wp = (const float4*)&s->Whh[row * 512];
    const float4* vp = (const float4*)hin;
    float acc = 0.f;
#pragma unroll
    for (int i = 0; i < 8; i++) {
        float4 w = wp[i * 16 + lane], v = vp[i * 16 + lane];
        acc += w.x * v.x + w.y * v.y + w.z * v.z + w.w * v.w;
    }
#pragma unroll
    for (int o = 8; o; o >>= 1) acc += __shfl_down_sync(0xffffffffu, acc, o, 16);
    if (lane == 0) s->gbuf[row] = acc + xc[row];
    __syncthreads();
    if (tid < 8) {
        float gi = s->gbuf[tid],      gf = s->gbuf[8 + tid];
        float gg = s->gbuf[16 + tid], go = s->gbuf[24 + tid];
        float c2 = sigf(gf) * s->cslice[tid] + sigf(gi) * tanhfast(gg);
        float h2 = sigf(go) * tanhfast(c2);
        s->cslice[tid] = c2;
        houtOwn[tid] = h2;
        pub64(pubBase + tid, h2, tag);
    }
    __syncthreads();
}

// 8 dots of an 8x512 smem matrix with v (threads 0..127), conflict-free.
__device__ __forceinline__ void attn_dot(const float* M, const float* v,
                                         float* dst, int tid) {
    if (tid < 128) {
        int r = tid >> 4, lane = tid & 15;
        const float4* mp = (const float4*)&M[r * 512];
        const float4* vp = (const float4*)v;
        float acc = 0.f;
#pragma unroll
        for (int i = 0; i < 8; i++) {
            float4 w = mp[i * 16 + lane], x = vp[i * 16 + lane];
            acc += w.x * x.x + w.y * x.y + w.z * x.z + w.w * x.w;
        }
#pragma unroll
        for (int o = 8; o; o >>= 1) acc += __shfl_down_sync(0xffffffffu, acc, o, 16);
        if (lane == 0) dst[r] = acc;
    }
}

// ----- warp-parallel categorical sample + lp + entropy (tid<32 only) -------
__device__ __forceinline__ void warp_sample(const float* vals, const float* g, int n,
                                            int* oIdx, float* oLp, float* oEnt, int lane) {
    const float NINF = __int_as_float(0xff800000);
    float v1 = (lane < n) ? vals[lane] : NINF;
    float d1 = (lane < n) ? v1 + g[lane] : NINF;
    int   i1 = lane;
    float v2 = NINF;
    if (lane == 0 && n > 32) {
        v2 = vals[32];
        float d2 = v2 + g[32];
        if (d2 > d1) { d1 = d2; i1 = 32; }
    }
#pragma unroll
    for (int off = 16; off; off >>= 1) {
        float dv = __shfl_down_sync(0xffffffffu, d1, off);
        int   di = __shfl_down_sync(0xffffffffu, i1, off);
        if (dv > d1 || (dv == d1 && di < i1)) { d1 = dv; i1 = di; }
    }
    int best = __shfl_sync(0xffffffffu, i1, 0);
    float m1 = (lane < n) ? v1 : NINF;
    if (lane == 0 && n > 32) m1 = fmaxf(m1, v2);
#pragma unroll
    for (int off = 16; off; off >>= 1) m1 = fmaxf(m1, __shfl_xor_sync(0xffffffffu, m1, off));
    float se = (lane < n) ? __expf(v1 - m1) : 0.f;
    if (lane == 0 && n > 32) se += __expf(v2 - m1);
#pragma unroll
    for (int off = 16; off; off >>= 1) se += __shfl_xor_sync(0xffffffffu, se, off);
    float lse = __logf(se);
    float ent = 0.f;
    if (lane < n)            { float l = v1 - m1 - lse; ent -= l * __expf(l); }
    if (lane == 0 && n > 32) { float l = v2 - m1 - lse; ent -= l * __expf(l); }
#pragma unroll
    for (int off = 16; off; off >>= 1) ent += __shfl_xor_sync(0xffffffffu, ent, off);
    if (lane == 0) {
        *oIdx = best;
        *oLp  = -(vals[best] - m1 - lse);
        *oEnt = ent;
    }
}

__global__ void __launch_bounds__(NT, 1)
controller_kernel(const float* __restrict__ emb,   const float* __restrict__ w_ih,
                  const float* __restrict__ w_hh,  const float* __restrict__ b_ih,
                  const float* __restrict__ b_hh,  const float* __restrict__ w1,
                  const float* __restrict__ w2,    const float* __restrict__ idxfc,
                  const float* __restrict__ opfc,  float* __restrict__ out) {
    if (blockIdx.x >= GRID) return;
    extern __shared__ __align__(16) float smraw[];
    SM* s = (SM*)smraw;
    const int tid = threadIdx.x;
    const int b   = blockIdx.x;

    // ---------------- setup ----------------
    if (tid == 0) {
        s->base = *(volatile unsigned*)&gEpochBase;
        s->sel = OPSN;
        s->lpSum = 0.f; s->entSum = 0.f;
        s->vals[32] = -1e9f;        // anchor 32 can never be valid (t<=31)
    }
    for (int i = tid; i < 32 * 512; i += NT) {
        int row = i >> 9, k = i & 511;
        int gate = row >> 3, jj = row & 7;
        int grow = gate * 512 + b * 8 + jj;
        s->Whh[i] = w_hh[grow * 512 + k];
        s->Wih[i] = w_ih[grow * 512 + k];
    }
    for (int i = tid; i < 8 * 512; i += NT) {
        int a = i >> 9, k = i & 511;
        s->A1[i]  = w1[(b * 8 + a) * 512 + k];
        s->A2T[i] = w2[k * 512 + b * 8 + a];
    }
    if (tid < OPSN * 8) {
        int o = tid >> 3, j = tid & 7;
        s->OPFT[tid] = opfc[o * 512 + b * 8 + j];
    }
    if (tid < 32) {
        int gate = tid >> 3, jj = tid & 7;
        int grow = gate * 512 + b * 8 + jj;
        float bb = b_ih[grow] + b_hh[grow];
        s->bias[tid]  = bb;
        s->anchG[tid] = bb;      // anchor 0 = zeros -> x-gates = bias
    }
    if (tid < 8) { s->idxfc8[tid] = idxfc[b * 8 + tid]; s->cslice[tid] = 0.f; }
    if (tid < LP1 * 8) s->anchW1[tid] = 0.f;
    __syncthreads();

    // embGates for all 17 embeddings
    {
        int row = tid >> 4, lane = tid & 15;
        const float4* wr = (const float4*)&s->Wih[row * 512];
        for (int e = 0; e < 17; e++) {
            const float4* er = (const float4*)&emb[e * 512];
            float acc = 0.f;
#pragma unroll
            for (int i = 0; i < 8; i++) {
                float4 w = wr[i * 16 + lane];
                float4 v = __ldg(&er[i * 16 + lane]);
                acc += w.x * v.x + w.y * v.y + w.z * v.z + w.w * v.w;
            }
#pragma unroll
            for (int o = 8; o; o >>= 1) acc += __shfl_down_sync(0xffffffffu, acc, o, 16);
            if (lane == 0) s->embG[e * 32 + row] = acc + s->bias[row];
        }
    }
    // key chain (data-independent)
    if (tid == 0) {
        unsigned k0 = 0u, k1 = 42u;
        for (int t = 0; t < NSTEP; t++) {
            s->keys2[2 * t] = k0; s->keys2[2 * t + 1] = k1;
            unsigned o0, o1; tf2x32(k0, k1, 0u, 2u, o0, o1);
            k0 = o0; k1 = o1;
        }
    }
    __syncthreads();
    for (int p = tid; p < NSTEP * (LP1 + OPSN); p += NT) {
        int t = p / (LP1 + OPSN), r = p % (LP1 + OPSN);
        unsigned K0 = s->keys2[2 * t], K1 = s->keys2[2 * t + 1];
        unsigned c0, c1, o0, o1;
        if (r < LP1) {
            tf2x32(K0, K1, 0u, 0u, c0, c1);
            tf2x32(c0, c1, 0u, (unsigned)r, o0, o1);
            s->gnode[t * LP1 + r] = gumbelf(o0 ^ o1);
        } else {
            int o = r - LP1;
            tf2x32(K0, K1, 0u, 1u, c0, c1);
            tf2x32(c0, c1, 0u, (unsigned)o, o0, o1);
            s->gop[t * OPSN + o] = gumbelf(o0 ^ o1);
        }
    }
    __syncthreads();
    const unsigned base = s->base;

    // ---------------- initial cell: h0 = cell(emb[16], 0, 0) ----------------
    if (tid < 8) {
        float gi = s->embG[16 * 32 + tid];
        float gg = s->embG[16 * 32 + 16 + tid], go = s->embG[16 * 32 + 24 + tid];
        float c2 = sigf(gi) * tanhfast(gg);
        float h2 = sigf(go) * tanhfast(c2);
        s->cslice[tid] = c2;
        pub64(&gPubI[b * 8 + tid], h2, base + 1);
    }
    {
        u64t w;
        do { w = ldrx(&gPubI[tid]); } while ((unsigned)(w >> 32) != base + 1);
        s->hprev[tid] = lo32(w);
    }
    __syncthreads();
    if (b == 0 && tid == 0) *(volatile unsigned*)&gEpochBase = base + 128;

    // ---------------- main loop ----------------
    for (int t = 0; t < NSTEP; t++) {
        const unsigned tag1 = base + 2 + 3 * t;
        const unsigned tag2 = tag1 + 1;
        const unsigned tag3 = tag1 + 2;

        // cell1: h1 = cell(emb[sel], hprev, c); tail publishes h1 slice early
        cell_hh(s, s->hprev, &s->embG[s->sel * 32], tid, &s->h1full[b * 8],
                &gPubH1[b * 8], tag1);

        // round-1 publish: attn partial for global dim `tid` from local slice
        {
            float pa = 0.f;
#pragma unroll
            for (int j = 0; j < 8; j++)
                pa += s->A2T[j * 512 + tid] * s->h1full[b * 8 + j];
            pub64(&gPubA[b * 512 + tid], pa, tag1);
        }

        // overlap round-1 latency: anchor-t x-gates + anchW1[t] from hprev
        if (t > 0) {
            int row = tid >> 4, lane = tid & 15;
            const float4* wp = (const float4*)&s->Wih[row * 512];
            const float4* vp = (const float4*)s->hprev;
            float acc = 0.f;
#pragma unroll
            for (int i = 0; i < 8; i++) {
                float4 w = wp[i * 16 + lane], v = vp[i * 16 + lane];
                acc += w.x * v.x + w.y * v.y + w.z * v.z + w.w * v.w;
            }
#pragma unroll
            for (int o = 8; o; o >>= 1) acc += __shfl_down_sync(0xffffffffu, acc, o, 16);
            if (lane == 0) s->anchG[t * 32 + row] = acc + s->bias[row];
        }
        attn_dot(s->A1, s->hprev, &s->anchW1[t * 8], tid);

        // consume round1 (fused hw2 reduce): warp w owns dim p=w>>1, half c's
        {
            int pA = tid >> 6, cA = tid & 63;
            const u64t* qa = &gPubA[cA * 512 + b * 8 + pA];
            const u64t* qh = &gPubH1[tid];
            float va = 0.f, vh = 0.f; unsigned got = 0;
            while (got != 3u) {
                u64t w;
                if (!(got & 1u)) { w = ldrx(qa); if ((unsigned)(w >> 32) == tag1) { va = lo32(w); got |= 1u; } }
                if (!(got & 2u)) { w = ldrx(qh); if ((unsigned)(w >> 32) == tag1) { vh = lo32(w); got |= 2u; } }
            }
            s->h1full[tid] = vh;
#pragma unroll
            for (int o = 16; o; o >>= 1) va += __shfl_down_sync(0xffffffffu, va, o);
            if ((tid & 31) == 0) s->attnP16[tid >> 5] = va;
        }
        __syncthreads();   // (B) h1full, attnP16, anchW1, anchG ready

        // round-2 publish: node-logit partials (warps 0..8, shuffle-reduced)
        if (tid < 288) {
            int a = tid >> 3; if (a > 32) a = 32;
            int rl = tid & 7;
            float hw2 = s->attnP16[2 * rl] + s->attnP16[2 * rl + 1];
            float q = tanhfast(s->anchW1[a * 8 + rl] + hw2) * s->idxfc8[rl];
#pragma unroll
            for (int o = 4; o; o >>= 1) q += __shfl_down_sync(0xffffffffu, q, o, 8);
            if (rl == 0 && tid < 264 && a <= t) pub64(&gPubL[a * 64 + b], q, tag2);
        }

        // cell2 matvec (depends only on h1full) — hidden in round-2 latency
        {
            int row = tid >> 4, lane = tid & 15;
            const float4* wp = (const float4*)&s->Whh[row * 512];
            const float4* vp = (const float4*)s->h1full;
            float acc = 0.f;
#pragma unroll
            for (int i = 0; i < 8; i++) {
                float4 w = wp[i * 16 + lane], v = vp[i * 16 + lane];
                acc += w.x * v.x + w.y * v.y + w.z * v.z + w.w * v.w;
            }
#pragma unroll
            for (int o = 8; o; o >>= 1) acc += __shfl_down_sync(0xffffffffu, acc, o, 16);
            if (lane == 0) s->gbuf[row] = acc;     // x-gates added in tail
        }

        // consume round2 (fused vals reduce): 16 lanes per anchor, 4 polls each
        {
            int a = tid >> 4, l = tid & 15;
            float v = 0.f;
            if (a <= t) {
                const u64t* base0 = &gPubL[a * 64 + l];
                float v0 = 0.f, v1 = 0.f, v2 = 0.f, v3 = 0.f; unsigned got = 0;
                while (got != 15u) {
                    u64t w;
                    if (!(got & 1u)) { w = ldrx(base0);      if ((unsigned)(w >> 32) == tag2) { v0 = lo32(w); got |= 1u; } }
                    if (!(got & 2u)) { w = ldrx(base0 + 16); if ((unsigned)(w >> 32) == tag2) { v1 = lo32(w); got |= 2u; } }
                    if (!(got & 4u)) { w = ldrx(base0 + 32); if ((unsigned)(w >> 32) == tag2) { v2 = lo32(w); got |= 4u; } }
                    if (!(got & 8u)) { w = ldrx(base0 + 48); if ((unsigned)(w >> 32) == tag2) { v3 = lo32(w); got |= 8u; } }
                }
                v = (v0 + v1) + (v2 + v3);
            }
#pragma unroll
            for (int o = 8; o; o >>= 1) v += __shfl_down_sync(0xffffffffu, v, o, 16);
            if (l == 0) s->vals[a] = (a <= t) ? 2.5f * tanhfast(v * 0.2f) : -1e9f;
        }
        __syncthreads();   // (E) vals + gbuf ready
        if (tid < 32)
            warp_sample(s->vals, &s->gnode[t * LP1], LP1,
                        &s->nodeIdx, &s->nodeLp, &s->nodeEnt, tid);
        __syncthreads();   // (F) nodeIdx known

        // cell2 tail + round-3 publish, all inside warp 0
        if (tid < 32) {
            if (tid < 8) {
                const float* ag = &s->anchG[s->nodeIdx * 32];
                float gi = s->gbuf[tid]      + ag[tid];
                float gf = s->gbuf[8 + tid]  + ag[8 + tid];
                float gg = s->gbuf[16 + tid] + ag[16 + tid];
                float go = s->gbuf[24 + tid] + ag[24 + tid];
                float c2 = sigf(gf) * s->cslice[tid] + sigf(gi) * tanhfast(gg);
                float h2 = sigf(go) * tanhfast(c2);
                s->cslice[tid] = c2;
                s->h2own[tid] = h2;
                pub64(&gPubO[b * 24 + tid], h2, tag3);
            }
            __syncwarp();
            if (tid < 16) {
                float oa = 0.f;
#pragma unroll
                for (int j = 0; j < 8; j++) oa += s->OPFT[tid * 8 + j] * s->h2own[j];
                pub64(&gPubO[b * 24 + 8 + tid], oa, tag3);
            }
        }

        // consume round3 (fused oplog reduce): h2 + per-op warp reductions
        {
            int o = tid >> 5, q = tid & 31;
            const u64t* qh = &gPubO[(tid >> 3) * 24 + (tid & 7)];
            const u64t* q0 = &gPubO[(2 * q) * 24 + 8 + o];
            const u64t* q1 = &gPubO[(2 * q + 1) * 24 + 8 + o];
            float vh = 0.f, p0 = 0.f, p1 = 0.f; unsigned got = 0;
            while (got != 7u) {
                u64t w;
                if (!(got & 1u)) { w = ldrx(qh); if ((unsigned)(w >> 32) == tag3) { vh = lo32(w); got |= 1u; } }
                if (!(got & 2u)) { w = ldrx(q0); if ((unsigned)(w >> 32) == tag3) { p0 = lo32(w); got |= 2u; } }
                if (!(got & 4u)) { w = ldrx(q1); if ((unsigned)(w >> 32) == tag3) { p1 = lo32(w); got |= 4u; } }
            }
            s->hprev[tid] = vh;
            float ps = p0 + p1;
#pragma unroll
            for (int off = 16; off; off >>= 1)
                ps += __shfl_xor_sync(0xffffffffu, ps, off);
            if (q == 0) s->oplog[o] = tanhfast(ps * 0.2f);
        }
        __syncthreads();   // (G)
        if (tid < 32) {
            warp_sample(s->oplog, &s->gop[t * OPSN], OPSN,
                        &s->opIdx, &s->opLp, &s->opEnt, tid);
            if (tid == 0) {
                s->lpSum  += s->nodeLp + s->opLp;
                s->entSum += s->nodeEnt + s->opEnt;
                s->sel = s->opIdx;
                if (b == 0) {
                    out[2 * t]     = (float)s->nodeIdx;
                    out[2 * t + 1] = (float)s->opIdx;
                }
            }
        }
        __syncthreads();   // (H)
    }

    if (b == 0 && tid == 0) { out[64] = s->entSum; out[65] = s->lpSum; }
}

extern "C" void kernel_launch(void* const* d_in, const int* in_sizes, int n_in,
                              void* d_out, int out_size) {
    (void)in_sizes; (void)n_in; (void)out_size;
    cudaFuncSetAttribute(controller_kernel,
                         cudaFuncAttributeMaxDynamicSharedMemorySize,
                         (int)sizeof(SM));
    controller_kernel<<<GRIDL, NT, sizeof(SM)>>>(
        (const float*)d_in[0],  // embedding
        (const float*)d_in[1],  // w_ih
        (const float*)d_in[2],  // w_hh
        (const float*)d_in[3],  // b_ih
        (const float*)d_in[4],  // b_hh
        (const float*)d_in[5],  // w_attn_1
        (const float*)d_in[6],  // w_attn_2
        (const float*)d_in[7],  // index_fc
        (const float*)d_in[8],  // op_fc
        (float*)d_out);
}